// round 9
// baseline (speedup 1.0000x reference)
#include <cuda_runtime.h>
#include <math.h>

#define KCODES 512
#define DDIM   64
#define HDIM   64
#define LN_EPS 1e-5f

#define NVB    64      // phase-1 (LUT) blocks
#define VPB    8       // token-values per LUT block
#define CCHUNK 64      // codes per smem chunk
#define NCH    8       // 512 / 64
#define GRID   2048    // total blocks
#define TPB    256     // threads per block

// device state (zero-initialized at module load; self-reset each replay)
__device__ float4 g_q_lut4[KCODES * 16];   // chosen codebook row per v
__device__ float  g_idx_f[KCODES];         // argmin index per v, as float
__device__ double g_err_lut[KCODES];       // ||cb[idx]-z_v||^2
__device__ int    g_cnt[KCODES];           // histogram of t
__device__ int    g_ticket;                // phase-1 completion ticket
__device__ int    g_ready;                 // LUT-ready flag
__device__ int    g_end;                   // end-of-kernel ticket

__global__ __launch_bounds__(TPB)
void fused_kernel(const float* __restrict__ W1,
                  const float* __restrict__ b1,
                  const float* __restrict__ lng,
                  const float* __restrict__ lnb,
                  const float* __restrict__ W2,
                  const float* __restrict__ b2,
                  const float* __restrict__ cb,
                  const int*   __restrict__ t,
                  float4*      __restrict__ q_out,
                  float*       __restrict__ idx_out,
                  float*       __restrict__ loss_out,
                  int n) {
    __shared__ float  h_sh[VPB * 65];
    __shared__ float  z_sh[VPB * 65];
    __shared__ float4 cb_sh4[CCHUNK * 17];     // padded: conflict-free LDS.128
    __shared__ float  s_mu[VPB], s_rs[VPB], s_z2[VPB];
    __shared__ float  s_e2[CCHUNK];
    __shared__ float  s_pd[VPB * 32];
    __shared__ int    s_pi[VPB * 32];
    __shared__ int    s_bestv[VPB];
    __shared__ int    sc[KCODES];
    __shared__ int    s_flag;
    __shared__ double dacc[TPB];

    const int tid = threadIdx.x;
    const int bid = blockIdx.x;

    // =====================================================================
    // PHASE 1 — blocks 0..63 build the 512-entry LUT + histogram + loss
    // =====================================================================
    if (bid < NVB) {
        const int v0 = bid * VPB;

        // ---- private histogram of this block's 1/64 slice of t ----
        sc[tid] = 0;
        sc[tid + 256] = 0;
        __syncthreads();
        {
            const int nq = n >> 2;
            const int4* t4 = reinterpret_cast<const int4*>(t);
            for (int j = bid * TPB + tid; j < nq; j += NVB * TPB) {
                const int4 vv = __ldg(&t4[j]);
                atomicAdd(&sc[vv.x], 1);
                atomicAdd(&sc[vv.y], 1);
                atomicAdd(&sc[vv.z], 1);
                atomicAdd(&sc[vv.w], 1);
            }
        }

        // ---- h = norm*W1 + b1 (2 items per thread) ----
        #pragma unroll
        for (int idx = tid; idx < VPB * HDIM; idx += TPB) {
            const int vl = idx >> 6, j = idx & 63;
            const float norm = ((float)(v0 + vl) / (float)(KCODES - 1)) * 2.0f - 1.0f;
            h_sh[vl * 65 + j] = norm * W1[j] + b1[j];
        }
        __syncthreads();

        // flush private histogram to global
        {
            const int c0 = sc[tid], c1 = sc[tid + 256];
            if (c0) atomicAdd(&g_cnt[tid], c0);
            if (c1) atomicAdd(&g_cnt[tid + 256], c1);
        }

        // ---- LN stats (sequential ascending j, one v per thread) ----
        if (tid < VPB) {
            float s = 0.0f;
            for (int j = 0; j < HDIM; j++) s += h_sh[tid * 65 + j];
            const float mu = s / (float)HDIM;
            float vs = 0.0f;
            for (int j = 0; j < HDIM; j++) {
                const float d = h_sh[tid * 65 + j] - mu;
                vs += d * d;
            }
            s_mu[tid] = mu;
            s_rs[tid] = 1.0f / sqrtf(vs / (float)HDIM + LN_EPS);
        }
        __syncthreads();

        // ---- LN + relu ----
        #pragma unroll
        for (int idx = tid; idx < VPB * HDIM; idx += TPB) {
            const int vl = idx >> 6, j = idx & 63;
            float x = (h_sh[vl * 65 + j] - s_mu[vl]) * s_rs[vl] * lng[j] + lnb[j];
            h_sh[vl * 65 + j] = fmaxf(x, 0.0f);
        }
        __syncthreads();

        // ---- z = h @ W2 + b2 (sequential ascending j) ----
        #pragma unroll
        for (int idx = tid; idx < VPB * DDIM; idx += TPB) {
            const int vl = idx >> 6, d = idx & 63;
            float acc = 0.0f;
            for (int j = 0; j < HDIM; j++)
                acc += h_sh[vl * 65 + j] * __ldg(&W2[j * DDIM + d]);
            z_sh[vl * 65 + d] = acc + b2[d];
        }
        __syncthreads();

        // ---- z2 (sequential ascending d) ----
        if (tid < VPB) {
            float s = 0.0f;
            for (int d = 0; d < DDIM; d++) {
                const float zz = z_sh[tid * 65 + d];
                s += zz * zz;
            }
            s_z2[tid] = s;
        }
        __syncthreads();

        // ---- distance sweep: 8 chunks of 64 codes ----
        const int vl = tid & 7;
        const int kg = tid >> 3;                // 0..31, 2 codes each
        const float* zrow = &z_sh[vl * 65];

        float bd = INFINITY;
        int   bi = 0;

        for (int c = 0; c < NCH; c++) {
            {
                const float4* src = reinterpret_cast<const float4*>(
                    cb + (size_t)(c * CCHUNK) * DDIM);
                #pragma unroll
                for (int j = tid; j < CCHUNK * 16; j += TPB)
                    cb_sh4[(j >> 4) * 17 + (j & 15)] = src[j];
            }
            if (tid < CCHUNK) {
                const float4* e = reinterpret_cast<const float4*>(
                    cb + (size_t)(c * CCHUNK + tid) * DDIM);
                float acc = 0.0f;
                #pragma unroll
                for (int i = 0; i < 16; i++) {
                    const float4 cc = e[i];
                    acc += cc.x * cc.x;
                    acc += cc.y * cc.y;
                    acc += cc.z * cc.z;
                    acc += cc.w * cc.w;
                }
                s_e2[tid] = acc;
            }
            __syncthreads();

            const int kl0 = kg * 2;
            const float4* e0 = &cb_sh4[kl0 * 17];
            const float4* e1 = &cb_sh4[(kl0 + 1) * 17];
            float dot0 = 0.0f, dot1 = 0.0f;
            #pragma unroll
            for (int i = 0; i < 16; i++) {
                const float4 a = e0[i];
                const float4 b = e1[i];
                const float z0 = zrow[4 * i + 0];
                const float z1 = zrow[4 * i + 1];
                const float z2r = zrow[4 * i + 2];
                const float z3 = zrow[4 * i + 3];
                dot0 += z0 * a.x; dot0 += z1 * a.y; dot0 += z2r * a.z; dot0 += z3 * a.w;
                dot1 += z0 * b.x; dot1 += z1 * b.y; dot1 += z2r * b.z; dot1 += z3 * b.w;
            }
            const float zz2 = s_z2[vl];
            const float d0 = zz2 - 2.0f * dot0 + s_e2[kl0];
            const float d1 = zz2 - 2.0f * dot1 + s_e2[kl0 + 1];
            const int   k  = c * CCHUNK + kl0;
            if (d0 < bd) { bd = d0; bi = k; }
            if (d1 < bd) { bd = d1; bi = k + 1; }
            __syncthreads();
        }

        s_pd[vl * 32 + kg] = bd;
        s_pi[vl * 32 + kg] = bi;
        __syncthreads();

        // ---- in-block argmin combine (ascending kg), err, idx ----
        if (tid < VPB) {
            const int v = v0 + tid;
            float bdv = INFINITY;
            int   biv = 0;
            for (int g = 0; g < 32; g++) {
                const float d2 = s_pd[tid * 32 + g];
                if (d2 < bdv) { bdv = d2; biv = s_pi[tid * 32 + g]; }
            }
            s_bestv[tid] = biv;
            g_idx_f[v]   = (float)biv;

            const float* e  = cb + (size_t)biv * DDIM;
            const float* zp = &z_sh[tid * 65];
            double a0 = 0.0, a1 = 0.0, a2 = 0.0, a3 = 0.0;
            for (int d = 0; d < DDIM; d += 4) {
                const double f0 = (double)e[d + 0] - (double)zp[d + 0];
                const double f1 = (double)e[d + 1] - (double)zp[d + 1];
                const double f2 = (double)e[d + 2] - (double)zp[d + 2];
                const double f3 = (double)e[d + 3] - (double)zp[d + 3];
                a0 += f0 * f0; a1 += f1 * f1; a2 += f2 * f2; a3 += f3 * f3;
            }
            g_err_lut[v] = (a0 + a1) + (a2 + a3);
        }
        __syncthreads();

        // ---- fill q LUT (2 floats per thread) ----
        {
            float* q_lut = reinterpret_cast<float*>(g_q_lut4);
            #pragma unroll
            for (int idx = tid; idx < VPB * DDIM; idx += TPB) {
                const int vl2 = idx >> 6, d = idx & 63;
                q_lut[(v0 + vl2) * DDIM + d] = cb[(size_t)s_bestv[vl2] * DDIM + d];
            }
        }

        // ---- phase-1 ticket; last block: loss + release flag ----
        __threadfence();
        if (tid == 0) {
            const int gt = atomicAdd(&g_ticket, 1);
            s_flag = (gt == NVB - 1) ? 1 : 0;
        }
        __syncthreads();
        if (s_flag) {
            __threadfence();
            if (loss_out != nullptr) {
                dacc[tid] = (double)g_cnt[tid]       * g_err_lut[tid]
                          + (double)g_cnt[tid + 256] * g_err_lut[tid + 256];
                __syncthreads();
                for (int off = 128; off > 0; off >>= 1) {
                    if (tid < off) dacc[tid] += dacc[tid + off];
                    __syncthreads();
                }
                if (tid == 0)
                    loss_out[0] = (float)(1.25 * dacc[0] / ((double)n * (double)DDIM));
            }
            __threadfence();
            if (tid == 0) {
                g_ticket = 0;                       // clean for next replay
                atomicExch(&g_ready, 1);            // release LUT
            }
        }
    }

    // =====================================================================
    // PHASE 2 — all blocks: wait for LUT, then scatter
    // =====================================================================
    if (tid == 0) {
        volatile int* rdy = &g_ready;
        while (*rdy == 0) __nanosleep(200);
    }
    __syncthreads();
    __threadfence();                                // acquire LUT/idx data

    {
        const int total  = n * 16;
        const int stride = GRID * TPB;
        const int i0     = bid * TPB + tid;

        for (int base = i0; base < total; base += stride * 4) {
            int    v[4];
            float4 val[4];
            #pragma unroll
            for (int j = 0; j < 4; j++) {
                const int i = base + j * stride;
                if (i < total) {
                    v[j]   = __ldg(t + (i >> 4));
                    val[j] = g_q_lut4[(v[j] << 4) + (i & 15)];
                } else {
                    v[j] = -1;
                }
            }
            #pragma unroll
            for (int j = 0; j < 4; j++) {
                const int i = base + j * stride;
                if (v[j] >= 0) {
                    q_out[i] = val[j];
                    if ((i & 15) == 0 && idx_out != nullptr)
                        idx_out[i >> 4] = g_idx_f[v[j]];
                }
            }
        }
    }

    // ---- end ticket: last block resets state for the next graph replay ----
    if (tid == 0) {
        const int e = atomicAdd(&g_end, 1);
        s_flag = (e == GRID - 1) ? 1 : 0;
    }
    __syncthreads();
    if (s_flag) {
        g_cnt[tid] = 0;
        g_cnt[tid + 256] = 0;
        if (tid == 0) {
            g_end = 0;
            atomicExch(&g_ready, 0);
        }
    }
}

// ---------------------------------------------------------------------------
extern "C" void kernel_launch(void* const* d_in, const int* in_sizes, int n_in,
                              void* d_out, int out_size) {
    const int*   t    = (const int*)d_in[0];
    const float* W1   = (const float*)d_in[1];
    const float* b1   = (const float*)d_in[2];
    const float* lng  = (const float*)d_in[3];
    const float* lnb  = (const float*)d_in[4];
    const float* W2   = (const float*)d_in[5];
    const float* b2   = (const float*)d_in[6];
    const float* cb   = (const float*)d_in[7];

    const int n = in_sizes[0];                 // N = B*T = 262144 tokens
    float* out = (float*)d_out;

    // Output layout: [ q : n*64 floats | idx : n floats | loss : 1 float ]
    const bool full = (out_size >= n * DDIM + n + 1);
    float* q_out    = out;
    float* idx_out  = full ? (out + (size_t)n * DDIM) : nullptr;
    float* loss_out = full ? (out + (size_t)n * DDIM + n) : nullptr;

    fused_kernel<<<GRID, TPB>>>(W1, b1, lng, lnb, W2, b2, cb, t,
                                (float4*)q_out, idx_out, loss_out, n);
}

// round 10
// speedup vs baseline: 1.0137x; 1.0137x over previous
#include <cuda_runtime.h>
#include <math.h>

#define KCODES 512
#define DDIM   64
#define HDIM   64
#define LN_EPS 1e-5f

#define VT     32      // token-values per LUT block
#define CHUNK  32      // codes per LUT block
#define NCHUNK 16      // 512 / 32
#define VTILES 16      // 512 / 32
#define NLUT   (VTILES * NCHUNK)   // 256 LUT blocks
#define TPB    256
#define GRID   888

// device state (zero-initialized at module load; self-reset each replay)
__device__ float4 g_q_lut4[KCODES * 16];   // chosen codebook row per v
__device__ float  g_idx_f[KCODES];         // argmin index per v, as float
__device__ double g_err_lut[KCODES];       // ||cb[idx]-z_v||^2
__device__ int    g_cnt[KCODES];           // histogram of t
__device__ float  g_z[KCODES * DDIM];      // encoder output per v
__device__ float  g_pd[KCODES * NCHUNK];   // partial best dist per (v,chunk)
__device__ int    g_pi[KCODES * NCHUNK];   // partial best idx  per (v,chunk)
__device__ int    g_tile_cnt[VTILES];      // per-vtile tickets
__device__ int    g_ticket;                // ticket among vtile-last blocks
__device__ int    g_ready;                 // LUT-ready flag
__device__ int    g_end;                   // end-of-kernel ticket

__global__ __launch_bounds__(TPB)
void fused_kernel(const float* __restrict__ W1,
                  const float* __restrict__ b1,
                  const float* __restrict__ lng,
                  const float* __restrict__ lnb,
                  const float* __restrict__ W2,
                  const float* __restrict__ b2,
                  const float* __restrict__ cb,
                  const int*   __restrict__ t,
                  float4*      __restrict__ q_out,
                  float*       __restrict__ idx_out,
                  float*       __restrict__ loss_out,
                  int n) {
    __shared__ float  h_sh[VT * 65];
    __shared__ float  z_sh[VT * 65];
    __shared__ float4 cb_sh4[CHUNK * 16];      // 8 KB, broadcast reads
    __shared__ float  s_mu[VT], s_rs[VT], s_z2[VT], s_e2[CHUNK];
    __shared__ float  s_pd[VT * 8];
    __shared__ int    s_pi[VT * 8];
    __shared__ int    s_last, s_flag;
    __shared__ int    s_bestv[VT];
    __shared__ int    sc[KCODES];
    __shared__ double dacc[TPB];

    const int tid = threadIdx.x;
    const int bid = blockIdx.x;

    // =====================================================================
    // PHASE 1 — blocks 0..255: R6-style LUT build (fastest measured).
    // Block = (v-tile of 32) x (code chunk of 32). All fp32 accumulations:
    // single accumulator, sequential ascending order, strict-< ascending-k
    // argmin — identical to all previous passing rounds.
    // =====================================================================
    if (bid < NLUT) {
        const int vtile = bid / NCHUNK;
        const int chunk = bid % NCHUNK;
        const int v0    = vtile * VT;
        const int k0    = chunk * CHUNK;

        // ---- private histogram of this block's 1/256 slice of t ----
        sc[tid] = 0;
        sc[tid + 256] = 0;
        __syncthreads();
        {
            const int nq = n >> 2;
            const int4* t4 = reinterpret_cast<const int4*>(t);
            for (int j = bid * TPB + tid; j < nq; j += NLUT * TPB) {
                const int4 vv = __ldg(&t4[j]);
                atomicAdd(&sc[vv.x], 1);
                atomicAdd(&sc[vv.y], 1);
                atomicAdd(&sc[vv.z], 1);
                atomicAdd(&sc[vv.w], 1);
            }
        }

        // ---- stage: h = norm*W1 + b1 ; codebook chunk -> smem ----
        for (int idx = tid; idx < VT * HDIM; idx += TPB) {
            const int vl = idx >> 6, j = idx & 63;
            const float norm = ((float)(v0 + vl) / (float)(KCODES - 1)) * 2.0f - 1.0f;
            h_sh[vl * 65 + j] = norm * W1[j] + b1[j];
        }
        {
            const float4* src = reinterpret_cast<const float4*>(cb + (size_t)k0 * DDIM);
            for (int j = tid; j < CHUNK * 16; j += TPB) cb_sh4[j] = src[j];
        }
        __syncthreads();

        // flush private histogram to global
        {
            const int c0 = sc[tid], c1 = sc[tid + 256];
            if (c0) atomicAdd(&g_cnt[tid], c0);
            if (c1) atomicAdd(&g_cnt[tid + 256], c1);
        }

        // ---- LN stats (sequential ascending j) ----
        if (tid < VT) {
            float s = 0.0f;
            for (int j = 0; j < HDIM; j++) s += h_sh[tid * 65 + j];
            const float mu = s / (float)HDIM;
            float vs = 0.0f;
            for (int j = 0; j < HDIM; j++) {
                const float d = h_sh[tid * 65 + j] - mu;
                vs += d * d;
            }
            s_mu[tid] = mu;
            s_rs[tid] = 1.0f / sqrtf(vs / (float)HDIM + LN_EPS);
        }
        __syncthreads();

        // ---- LN + relu ----
        for (int idx = tid; idx < VT * HDIM; idx += TPB) {
            const int vl = idx >> 6, j = idx & 63;
            float x = (h_sh[vl * 65 + j] - s_mu[vl]) * s_rs[vl] * lng[j] + lnb[j];
            h_sh[vl * 65 + j] = fmaxf(x, 0.0f);
        }
        __syncthreads();

        // ---- z = h @ W2 + b2 (sequential ascending j) ----
        for (int idx = tid; idx < VT * DDIM; idx += TPB) {
            const int vl = idx >> 6, d = idx & 63;
            float acc = 0.0f;
            for (int j = 0; j < HDIM; j++)
                acc += h_sh[vl * 65 + j] * __ldg(&W2[j * DDIM + d]);
            z_sh[vl * 65 + d] = acc + b2[d];
        }
        __syncthreads();

        // ---- z2 (warp 0), e2 per code (warp 1), persist z (chunk 0) ----
        if (tid < VT) {
            float s = 0.0f;
            for (int d = 0; d < DDIM; d++) {
                const float zz = z_sh[tid * 65 + d];
                s += zz * zz;
            }
            s_z2[tid] = s;
        } else if (tid < VT + CHUNK) {
            const int kl = tid - VT;
            const float4* e = reinterpret_cast<const float4*>(cb + (size_t)(k0 + kl) * DDIM);
            float acc = 0.0f;
            #pragma unroll
            for (int i = 0; i < DDIM / 4; i++) {
                const float4 c = e[i];
                acc += c.x * c.x;
                acc += c.y * c.y;
                acc += c.z * c.z;
                acc += c.w * c.w;
            }
            s_e2[kl] = acc;
        }
        if (chunk == 0) {
            for (int idx = tid; idx < VT * DDIM; idx += TPB) {
                const int vl = idx >> 6, d = idx & 63;
                g_z[(v0 + vl) * DDIM + d] = z_sh[vl * 65 + d];
            }
        }
        __syncthreads();

        // ---- dot products: thread (vl, kg) handles 4 contiguous codes ----
        const int vl = tid & 31;
        const int kg = tid >> 5;

        float dot0 = 0.0f, dot1 = 0.0f, dot2 = 0.0f, dot3 = 0.0f;
        #pragma unroll
        for (int ch = 0; ch < 4; ch++) {               // d-chunks of 16
            float zz[16];
            #pragma unroll
            for (int q = 0; q < 16; q++) zz[q] = z_sh[vl * 65 + ch * 16 + q];
            #pragma unroll
            for (int c = 0; c < 4; c++) {
                const float4* e = &cb_sh4[(kg * 4 + c) * 16 + ch * 4];
                float* dp = (c == 0) ? &dot0 : (c == 1) ? &dot1 : (c == 2) ? &dot2 : &dot3;
                #pragma unroll
                for (int i = 0; i < 4; i++) {
                    const float4 cc = e[i];
                    *dp += zz[i * 4 + 0] * cc.x;
                    *dp += zz[i * 4 + 1] * cc.y;
                    *dp += zz[i * 4 + 2] * cc.z;
                    *dp += zz[i * 4 + 3] * cc.w;
                }
            }
        }
        const float z2 = s_z2[vl];
        float bestD = INFINITY;
        int   bestI = 0;
        {
            float dists[4] = {z2 - 2.0f * dot0 + s_e2[kg * 4 + 0],
                              z2 - 2.0f * dot1 + s_e2[kg * 4 + 1],
                              z2 - 2.0f * dot2 + s_e2[kg * 4 + 2],
                              z2 - 2.0f * dot3 + s_e2[kg * 4 + 3]};
            #pragma unroll
            for (int c = 0; c < 4; c++) {
                if (dists[c] < bestD) { bestD = dists[c]; bestI = k0 + kg * 4 + c; }
            }
        }
        s_pd[vl * 8 + kg] = bestD;
        s_pi[vl * 8 + kg] = bestI;
        __syncthreads();

        // combine across kg ascending, publish chunk partials
        if (tid < VT) {
            float bd = INFINITY;
            int   bi = 0;
            for (int g = 0; g < 8; g++) {
                const float d2 = s_pd[tid * 8 + g];
                if (d2 < bd) { bd = d2; bi = s_pi[tid * 8 + g]; }
            }
            g_pd[(v0 + tid) * NCHUNK + chunk] = bd;
            g_pi[(v0 + tid) * NCHUNK + chunk] = bi;
        }

        // ---- per-vtile last block: combine chunks, fill LUTs ----
        __threadfence();
        if (tid == 0) {
            const int ticket = atomicAdd(&g_tile_cnt[vtile], 1);
            s_last = (ticket == NCHUNK - 1) ? 1 : 0;
        }
        __syncthreads();

        if (s_last) {
            __threadfence();
            if (tid < VT) {
                const int v = v0 + tid;
                float bd = INFINITY;
                int   bi = 0;
                for (int c = 0; c < NCHUNK; c++) {     // ascending chunk
                    const float d = g_pd[v * NCHUNK + c];
                    if (d < bd) { bd = d; bi = g_pi[v * NCHUNK + c]; }
                }
                s_bestv[tid] = bi;
                g_idx_f[v]   = (float)bi;

                const float* e  = cb + (size_t)bi * DDIM;
                const float* zp = g_z + v * DDIM;
                double a0 = 0.0, a1 = 0.0, a2 = 0.0, a3 = 0.0;
                for (int d = 0; d < DDIM; d += 4) {
                    const double f0 = (double)e[d + 0] - (double)zp[d + 0];
                    const double f1 = (double)e[d + 1] - (double)zp[d + 1];
                    const double f2 = (double)e[d + 2] - (double)zp[d + 2];
                    const double f3 = (double)e[d + 3] - (double)zp[d + 3];
                    a0 += f0 * f0; a1 += f1 * f1; a2 += f2 * f2; a3 += f3 * f3;
                }
                g_err_lut[v] = (a0 + a1) + (a2 + a3);
            }
            __syncthreads();

            float* q_lut = reinterpret_cast<float*>(g_q_lut4);
            for (int idx = tid; idx < VT * DDIM; idx += TPB) {
                const int vvl = idx >> 6, d = idx & 63;
                q_lut[(v0 + vvl) * DDIM + d] = cb[(size_t)s_bestv[vvl] * DDIM + d];
            }
            if (tid == 0) g_tile_cnt[vtile] = 0;       // clean for next replay

            // ---- ticket-of-tickets among the 16 vtile-last blocks ----
            __threadfence();
            if (tid == 0) {
                const int gt = atomicAdd(&g_ticket, 1);
                s_flag = (gt == VTILES - 1) ? 1 : 0;
            }
            __syncthreads();
            if (s_flag) {
                // release scatter FIRST, then compute the loss in parallel
                __threadfence();
                if (tid == 0) {
                    g_ticket = 0;
                    atomicExch(&g_ready, 1);
                }
                if (loss_out != nullptr) {
                    dacc[tid] = (double)g_cnt[tid]       * g_err_lut[tid]
                              + (double)g_cnt[tid + 256] * g_err_lut[tid + 256];
                    __syncthreads();
                    for (int off = 128; off > 0; off >>= 1) {
                        if (tid < off) dacc[tid] += dacc[tid + off];
                        __syncthreads();
                    }
                    if (tid == 0)
                        loss_out[0] = (float)(1.25 * dacc[0] /
                                              ((double)n * (double)DDIM));
                }
            }
        }
    }

    // =====================================================================
    // PHASE 2 — all blocks: wait for LUT, then scatter (proven pattern)
    // =====================================================================
    if (tid == 0) {
        volatile int* rdy = &g_ready;
        while (*rdy == 0) __nanosleep(100);
    }
    __syncthreads();
    __threadfence();                                   // acquire LUT/idx data

    {
        const int total  = n * 16;
        const int stride = gridDim.x * blockDim.x;
        const int i0     = bid * blockDim.x + tid;

        for (int base = i0; base < total; base += stride * 4) {
            int    v[4];
            float4 val[4];
            #pragma unroll
            for (int j = 0; j < 4; j++) {
                const int i = base + j * stride;
                if (i < total) {
                    v[j]   = __ldg(t + (i >> 4));
                    val[j] = g_q_lut4[(v[j] << 4) + (i & 15)];
                } else {
                    v[j] = -1;
                }
            }
            #pragma unroll
            for (int j = 0; j < 4; j++) {
                const int i = base + j * stride;
                if (v[j] >= 0) {
                    q_out[i] = val[j];
                    if ((i & 15) == 0 && idx_out != nullptr)
                        idx_out[i >> 4] = g_idx_f[v[j]];
                }
            }
        }
    }

    // ---- end ticket: last block resets state for the next graph replay ----
    if (tid == 0) {
        const int e = atomicAdd(&g_end, 1);
        s_flag = (e == (int)gridDim.x - 1) ? 1 : 0;
    }
    __syncthreads();
    if (s_flag) {
        g_cnt[tid] = 0;
        g_cnt[tid + 256] = 0;
        if (tid == 0) {
            g_end = 0;
            atomicExch(&g_ready, 0);
        }
    }
}

// ---------------------------------------------------------------------------
extern "C" void kernel_launch(void* const* d_in, const int* in_sizes, int n_in,
                              void* d_out, int out_size) {
    const int*   t    = (const int*)d_in[0];
    const float* W1   = (const float*)d_in[1];
    const float* b1   = (const float*)d_in[2];
    const float* lng  = (const float*)d_in[3];
    const float* lnb  = (const float*)d_in[4];
    const float* W2   = (const float*)d_in[5];
    const float* b2   = (const float*)d_in[6];
    const float* cb   = (const float*)d_in[7];

    const int n = in_sizes[0];                 // N = B*T = 262144 tokens
    float* out = (float*)d_out;

    // Output layout: [ q : n*64 floats | idx : n floats | loss : 1 float ]
    const bool full = (out_size >= n * DDIM + n + 1);
    float* q_out    = out;
    float* idx_out  = full ? (out + (size_t)n * DDIM) : nullptr;
    float* loss_out = full ? (out + (size_t)n * DDIM + n) : nullptr;

    fused_kernel<<<GRID, TPB>>>(W1, b1, lng, lnb, W2, b2, cb, t,
                                (float4*)q_out, idx_out, loss_out, n);
}